// round 8
// baseline (speedup 1.0000x reference)
#include <cuda_runtime.h>
#include <cuda_bf16.h>
#include <stdint.h>
#include <math.h>

#define VOCAB 32000
#define HID   512
#define EMB   256
#define NB    256
#define LEN   512

#define CL    8            // h-tile CTAs per n-tile (barrier group size)
#define NTILE 16           // n rows per block
#define HTILE 64           // h cols per block
#define NT    16           // number of n-tiles
#define GRID  128
#define NTHR  512

typedef unsigned long long u64;

// Scratch (static device allocations are allowed; runtime allocs are not).
__device__ float g_P[VOCAB * HID];          // P = emb @ Wxh^T + Wxh_b  (65.5 MB)
__device__ float g_h[2][NB * HID];          // ping-pong hidden state
__device__ unsigned g_cnt[NT * 64];         // per-n-tile arrive counters (256B apart)
__device__ unsigned g_gen[NT * 64];         // per-n-tile generation words (256B apart)

// Packed fp32x2 FMA (B300 packed pipe; ptxas never emits this from C++).
__device__ __forceinline__ u64 ffma2(u64 a, u64 b, u64 c) {
    u64 d;
    asm("fma.rn.f32x2 %0, %1, %2, %3;" : "=l"(d) : "l"(a), "l"(b), "l"(c));
    return d;
}

// ---------------------------------------------------------------------------
// proj_kernel: g_P[v,h] = sum_e emb[v,e] * Wxh_w[h,e] + Wxh_b[h]   (FFMA2)
// ---------------------------------------------------------------------------
__global__ void proj_kernel(const float* __restrict__ emb,
                            const float* __restrict__ Wxh_w,
                            const float* __restrict__ Wxh_b) {
    const int K   = EMB;
    const int STR = EMB + 4;
    extern __shared__ float sm[];
    float* As  = sm;
    float* Ws  = sm + 32 * STR;
    float* red = sm + 64 * STR;

    const int tid = threadIdx.x;
    const int v0  = blockIdx.x * 32;
    const int h0  = blockIdx.y * 32;

    const int NV4 = 32 * (K / 4);
    for (int idx = tid; idx < NV4; idx += 256) {
        int r  = idx / (K / 4);
        int c4 = (idx % (K / 4)) * 4;
        *(float4*)&As[r * STR + c4] = *(const float4*)&emb[(size_t)(v0 + r) * K + c4];
        *(float4*)&Ws[r * STR + c4] = *(const float4*)&Wxh_w[(size_t)(h0 + r) * K + c4];
    }
    __syncthreads();

    const int lane = tid & 31, kg = tid >> 5;
    const int ln = lane & 7, lh = lane >> 3;
    const int kb = kg * (K / 8);

    u64 acc[4][8];
#pragma unroll
    for (int i = 0; i < 4; i++)
#pragma unroll
        for (int j = 0; j < 8; j++) acc[i][j] = 0ULL;

#pragma unroll 4
    for (int kk = 0; kk < K / 8; kk += 4) {
        float4 av[4], wv[8];
#pragma unroll
        for (int i = 0; i < 4; i++)
            av[i] = *(const float4*)&As[(ln + 8 * i) * STR + kb + kk];
#pragma unroll
        for (int j = 0; j < 8; j++)
            wv[j] = *(const float4*)&Ws[(lh + 4 * j) * STR + kb + kk];
#pragma unroll
        for (int i = 0; i < 4; i++) {
            u64 alo = ((const u64*)&av[i])[0], ahi = ((const u64*)&av[i])[1];
#pragma unroll
            for (int j = 0; j < 8; j++) {
                u64 wlo = ((const u64*)&wv[j])[0], whi = ((const u64*)&wv[j])[1];
                acc[i][j] = ffma2(alo, wlo, acc[i][j]);
                acc[i][j] = ffma2(ahi, whi, acc[i][j]);
            }
        }
    }

#pragma unroll
    for (int i = 0; i < 4; i++)
#pragma unroll
        for (int j = 0; j < 8; j++) {
            float2 f = *(float2*)&acc[i][j];
            red[kg * 1152 + (ln + 8 * i) * 36 + (lh + 4 * j)] = f.x + f.y;
        }
    __syncthreads();

    const int o_n = tid >> 3, o_h = (tid & 7) * 4;
    float4 s = make_float4(0.f, 0.f, 0.f, 0.f);
#pragma unroll
    for (int g = 0; g < 8; g++) {
        float4 p = *(const float4*)&red[g * 1152 + o_n * 36 + o_h];
        s.x += p.x; s.y += p.y; s.z += p.z; s.w += p.w;
    }
    float4 b4 = *(const float4*)&Wxh_b[h0 + o_h];
    s.x += b4.x; s.y += b4.y; s.z += b4.z; s.w += b4.w;
    *(float4*)&g_P[(size_t)(v0 + o_n) * HID + h0 + o_h] = s;
}

// ---------------------------------------------------------------------------
// rnn_kernel: ONE persistent launch, all 512 timesteps. NO clusters.
//   128 CTAs = 16 n-tiles x 8 h-tiles, 16n x 64h per CTA.
//   Lane owns CONTIGUOUS h-pair (h0+2*lane, h0+2*lane+1) -> 8B epilogue ops.
//   Per-step critical-path cuts vs R7 baseline:
//     * cp.async in 2 commit groups; compute half 0 under half 1's arrival
//     * per-warp gen polling (no trailing block barrier)
//     * next step's X/P prefetched before the barrier spin (g_P immutable)
// ---------------------------------------------------------------------------
__global__ void __launch_bounds__(NTHR, 1)
rnn_kernel(const int*   __restrict__ X,
           const float* __restrict__ Whh_w,
           const float* __restrict__ Whh_b,
           float*       __restrict__ out)
{
    extern __shared__ float sm[];
    float*  sm_h   = sm;                       // [16 w][16 n][32 k]   32 KB
    float2* sm_red = (float2*)(sm + 16 * 512); // [16 kg][16 n][32 l]  64 KB

    const int tid  = threadIdx.x;
    const int w    = tid >> 5;
    const int lane = tid & 31;
    const int tile = blockIdx.x >> 3;          // n-tile id (barrier group)
    const int n0   = tile * NTILE;
    const int h0   = (blockIdx.x & 7) * HTILE;
    const int hA   = h0 + 2 * lane;            // contiguous h pair
    const int hB   = hA + 1;

    // --- persistent weight registers: rows hA,hB, k in [32w, 32w+32) -------
    u64 wA[16], wB[16];
    {
        const u64* pa = (const u64*)&Whh_w[(size_t)hA * HID + w * 32];
        const u64* pb = (const u64*)&Whh_w[(size_t)hB * HID + w * 32];
#pragma unroll
        for (int i = 0; i < 16; i++) { wA[i] = pa[i]; wB[i] = pb[i]; }
    }

    unsigned gen0 = 0;
    if (lane == 0)
        asm volatile("ld.acquire.gpu.u32 %0, [%1];"
                     : "=r"(gen0) : "l"(&g_gen[tile * 64]));

    unsigned int smem_w_base;
    {
        unsigned int a;
        asm("{ .reg .u64 t; cvta.to.shared.u64 t, %1; cvt.u32.u64 %0, t; }"
            : "=r"(a) : "l"(sm_h + w * 512));
        smem_w_base = a;
    }

    // epilogue ownership: thread (en, el) -> row n0+en, h-pair h0+2*el
    const int   en   = tid >> 5;
    const int   el   = tid & 31;
    const int   enab = n0 + en;
    const float2 ebv = *(const float2*)&Whh_b[h0 + 2 * el];

    // preload step-0 gather
    float2 pv;
    {
        int xid = __ldg(&X[enab * LEN]);
        pv = __ldg((const float2*)&g_P[(size_t)xid * HID + h0 + 2 * el]);
    }

    for (int t = 0; t < LEN; t++) {
        const float* hin = (t & 1) ? g_h[0] : g_h[1];
        float* dst = (t == LEN - 1) ? out : ((t & 1) ? g_h[1] : g_h[0]);

        float sA = 0.f, sB = 0.f;

        if (t > 0) {
            // --- warp-private async load, two commit groups (rows 0-7, 8-15)
#pragma unroll
            for (int half = 0; half < 2; half++) {
#pragma unroll
                for (int i = 0; i < 2; i++) {
                    int c  = half * 64 + i * 32 + lane;   // 16B chunk (0..127)
                    int n  = c >> 3;
                    int kq = c & 7;
                    const float* src =
                        &hin[(size_t)(n0 + n) * HID + w * 32 + kq * 4];
                    asm volatile("cp.async.cg.shared.global [%0], [%1], 16;"
                                 :: "r"(smem_w_base + c * 16), "l"(src) : "memory");
                }
                asm volatile("cp.async.commit_group;" ::: "memory");
            }

            // --- compute half 0 while half 1 is still in flight --------------
#pragma unroll
            for (int half = 0; half < 2; half++) {
                if (half == 0)
                    asm volatile("cp.async.wait_group 1;" ::: "memory");
                else
                    asm volatile("cp.async.wait_group 0;" ::: "memory");

                u64 aA[8], aB[8];
#pragma unroll
                for (int n = 0; n < 8; n++) { aA[n] = 0ULL; aB[n] = 0ULL; }
                const float* hp = sm_h + w * 512 + half * 8 * 32;
#pragma unroll
                for (int n = 0; n < 8; n++) {
                    const float4* row = (const float4*)(hp + n * 32);
                    u64 a0 = aA[n], a1 = aB[n];
#pragma unroll
                    for (int j = 0; j < 8; j++) {
                        float4 hv = row[j];
                        u64 lo = ((const u64*)&hv)[0];
                        u64 hi = ((const u64*)&hv)[1];
                        a0 = ffma2(lo, wA[2 * j],     a0);
                        a0 = ffma2(hi, wA[2 * j + 1], a0);
                        a1 = ffma2(lo, wB[2 * j],     a1);
                        a1 = ffma2(hi, wB[2 * j + 1], a1);
                    }
                    aA[n] = a0; aB[n] = a1;
                }
#pragma unroll
                for (int n = 0; n < 8; n++) {
                    float2 fa = *(float2*)&aA[n];
                    float2 fb = *(float2*)&aB[n];
                    sm_red[w * 512 + (half * 8 + n) * 32 + lane] =
                        make_float2(fa.x + fa.y, fb.x + fb.y);
                }
            }
            __syncthreads();

            // --- k-group reduction: one (n, h-pair) output per thread --------
            float xa = 0.f, xb = 0.f, ya = 0.f, yb = 0.f;
#pragma unroll
            for (int g = 0; g < 16; g += 2) {
                float2 v0 = sm_red[g * 512 + tid];
                float2 v1 = sm_red[(g + 1) * 512 + tid];
                xa += v0.x; xb += v0.y;
                ya += v1.x; yb += v1.y;
            }
            sA = xa + ya; sB = xb + yb;
        }

        // --- fused epilogue: bias + P + tanh, one 8B store -------------------
        float2 o;
        o.x = tanhf(sA + ebv.x + pv.x);
        o.y = tanhf(sB + ebv.y + pv.y);
        *(float2*)&dst[(size_t)enab * HID + h0 + 2 * el] = o;

        if (t < LEN - 1) {
            // --- prefetch next step's gather (g_P immutable; hides under spin)
            int xid2 = __ldg(&X[enab * LEN + t + 1]);
            pv = __ldg((const float2*)&g_P[(size_t)xid2 * HID + h0 + 2 * el]);

            __syncthreads();                  // all epilogue stores issued
            unsigned target = gen0 + (unsigned)t + 1;
            if (tid == 0) {
                unsigned old;
                asm volatile("atom.acq_rel.gpu.global.add.u32 %0, [%1], %2;"
                             : "=r"(old)
                             : "l"(&g_cnt[tile * 64]), "r"(1u) : "memory");
                if (old == CL - 1) {
                    asm volatile("st.relaxed.gpu.u32 [%0], %1;"
                                 :: "l"(&g_cnt[tile * 64]), "r"(0u) : "memory");
                    asm volatile("st.release.gpu.u32 [%0], %1;"
                                 :: "l"(&g_gen[tile * 64]), "r"(target) : "memory");
                } else {
                    unsigned g;
                    do {
                        asm volatile("ld.acquire.gpu.u32 %0, [%1];"
                                     : "=r"(g) : "l"(&g_gen[tile * 64]) : "memory");
                    } while ((int)(g - target) < 0);
                }
            } else if (lane == 0) {
                // per-warp poll: warp proceeds the moment the release lands
                unsigned g;
                do {
                    asm volatile("ld.acquire.gpu.u32 %0, [%1];"
                                 : "=r"(g) : "l"(&g_gen[tile * 64]) : "memory");
                } while ((int)(g - target) < 0);
            }
            __syncwarp();
        }
    }
}

// ---------------------------------------------------------------------------
extern "C" void kernel_launch(void* const* d_in, const int* in_sizes, int n_in,
                              void* d_out, int out_size) {
    const int*   X     = (const int*)d_in[0];
    const float* emb   = (const float*)d_in[1];
    const float* Whh_w = (const float*)d_in[2];
    const float* Whh_b = (const float*)d_in[3];
    const float* Wxh_w = (const float*)d_in[4];
    const float* Wxh_b = (const float*)d_in[5];
    float* out = (float*)d_out;

    const size_t sm_proj = (size_t)(64 * (EMB + 4) + 8 * 32 * 36) * sizeof(float); // ~101 KB
    const size_t sm_rnn  = (size_t)(16 * 512) * sizeof(float)                      // 32 KB h
                         + (size_t)(16 * 512) * sizeof(float2);                    // 64 KB red
    cudaFuncSetAttribute(proj_kernel, cudaFuncAttributeMaxDynamicSharedMemorySize, (int)sm_proj);
    cudaFuncSetAttribute(rnn_kernel,  cudaFuncAttributeMaxDynamicSharedMemorySize, (int)sm_rnn);

    // 1) P = emb @ Wxh^T + Wxh_b
    proj_kernel<<<dim3(VOCAB / 32, HID / 32), 256, sm_proj>>>(emb, Wxh_w, Wxh_b);

    // 2) all 512 timesteps in one persistent launch
    rnn_kernel<<<GRID, NTHR, sm_rnn>>>(X, Whh_w, Whh_b, out);
}

// round 9
// speedup vs baseline: 1.1839x; 1.1839x over previous
#include <cuda_runtime.h>
#include <cuda_bf16.h>
#include <stdint.h>
#include <math.h>

#define VOCAB 32000
#define HID   512
#define EMB   256
#define NB    256
#define LEN   512

#define CL    8            // h-tile CTAs per n-tile (flag group size)
#define NTILE 16           // n rows per block
#define HTILE 64           // h cols per block
#define NT    16           // number of n-tiles
#define GRID  128
#define NTHR  512

typedef unsigned long long u64;

// Scratch (static device allocations are allowed; runtime allocs are not).
__device__ float g_P[VOCAB * HID];            // P = emb @ Wxh^T + b  (65.5 MB)
__device__ float g_h[2][NB * HID];            // ping-pong hidden state
__device__ unsigned g_flag[NT * CL * 64];     // per-producer flags, 256B apart
__device__ unsigned g_cnt[NT * 64];           // end-of-kernel cleanup counters

// Packed fp32x2 FMA (B300 packed pipe; ptxas never emits this from C++).
__device__ __forceinline__ u64 ffma2(u64 a, u64 b, u64 c) {
    u64 d;
    asm("fma.rn.f32x2 %0, %1, %2, %3;" : "=l"(d) : "l"(a), "l"(b), "l"(c));
    return d;
}

// ---------------------------------------------------------------------------
// proj_kernel: g_P[v,h] = sum_e emb[v,e] * Wxh_w[h,e] + Wxh_b[h]   (FFMA2)
// ---------------------------------------------------------------------------
__global__ void proj_kernel(const float* __restrict__ emb,
                            const float* __restrict__ Wxh_w,
                            const float* __restrict__ Wxh_b) {
    const int K   = EMB;
    const int STR = EMB + 4;
    extern __shared__ float sm[];
    float* As  = sm;
    float* Ws  = sm + 32 * STR;
    float* red = sm + 64 * STR;

    const int tid = threadIdx.x;
    const int v0  = blockIdx.x * 32;
    const int h0  = blockIdx.y * 32;

    const int NV4 = 32 * (K / 4);
    for (int idx = tid; idx < NV4; idx += 256) {
        int r  = idx / (K / 4);
        int c4 = (idx % (K / 4)) * 4;
        *(float4*)&As[r * STR + c4] = *(const float4*)&emb[(size_t)(v0 + r) * K + c4];
        *(float4*)&Ws[r * STR + c4] = *(const float4*)&Wxh_w[(size_t)(h0 + r) * K + c4];
    }
    __syncthreads();

    const int lane = tid & 31, kg = tid >> 5;
    const int ln = lane & 7, lh = lane >> 3;
    const int kb = kg * (K / 8);

    u64 acc[4][8];
#pragma unroll
    for (int i = 0; i < 4; i++)
#pragma unroll
        for (int j = 0; j < 8; j++) acc[i][j] = 0ULL;

#pragma unroll 4
    for (int kk = 0; kk < K / 8; kk += 4) {
        float4 av[4], wv[8];
#pragma unroll
        for (int i = 0; i < 4; i++)
            av[i] = *(const float4*)&As[(ln + 8 * i) * STR + kb + kk];
#pragma unroll
        for (int j = 0; j < 8; j++)
            wv[j] = *(const float4*)&Ws[(lh + 4 * j) * STR + kb + kk];
#pragma unroll
        for (int i = 0; i < 4; i++) {
            u64 alo = ((const u64*)&av[i])[0], ahi = ((const u64*)&av[i])[1];
#pragma unroll
            for (int j = 0; j < 8; j++) {
                u64 wlo = ((const u64*)&wv[j])[0], whi = ((const u64*)&wv[j])[1];
                acc[i][j] = ffma2(alo, wlo, acc[i][j]);
                acc[i][j] = ffma2(ahi, whi, acc[i][j]);
            }
        }
    }

#pragma unroll
    for (int i = 0; i < 4; i++)
#pragma unroll
        for (int j = 0; j < 8; j++) {
            float2 f = *(float2*)&acc[i][j];
            red[kg * 1152 + (ln + 8 * i) * 36 + (lh + 4 * j)] = f.x + f.y;
        }
    __syncthreads();

    const int o_n = tid >> 3, o_h = (tid & 7) * 4;
    float4 s = make_float4(0.f, 0.f, 0.f, 0.f);
#pragma unroll
    for (int g = 0; g < 8; g++) {
        float4 p = *(const float4*)&red[g * 1152 + o_n * 36 + o_h];
        s.x += p.x; s.y += p.y; s.z += p.z; s.w += p.w;
    }
    float4 b4 = *(const float4*)&Wxh_b[h0 + o_h];
    s.x += b4.x; s.y += b4.y; s.z += b4.z; s.w += b4.w;
    *(float4*)&g_P[(size_t)(v0 + o_n) * HID + h0 + o_h] = s;
}

// ---------------------------------------------------------------------------
// rnn_kernel: ONE persistent launch, all 512 timesteps.
//   128 CTAs = 16 n-tiles x 8 h-tiles, 16n x 64h per CTA.
//   Sync = per-PRODUCER flags: CTA j publishes flag[j]=t+1 after its step-t
//   epilogue; consumer warp w polls only flag[w>>1] (its sole producer), then
//   cp.asyncs its 16n x 32k slice. Own-CTA warps (2j, 2j+1) get their slice
//   through SMEM written by the epilogue and skip polling entirely.
//   Flags are monotonic within a launch; the group's last-finishing CTA
//   resets them at kernel end (deterministic across graph replays).
// ---------------------------------------------------------------------------
__global__ void __launch_bounds__(NTHR, 1)
rnn_kernel(const int*   __restrict__ X,
           const float* __restrict__ Whh_w,
           const float* __restrict__ Whh_b,
           float*       __restrict__ out)
{
    extern __shared__ float sm[];
    float*  sm_h   = sm;                       // [16 w][16 n][32 k]   32 KB
    float2* sm_red = (float2*)(sm + 16 * 512); // [16 kg][16 n][32 l]  64 KB

    const int tid   = threadIdx.x;
    const int w     = tid >> 5;
    const int lane  = tid & 31;
    const int tile  = blockIdx.x >> 3;         // n-tile id (flag group)
    const int j_own = blockIdx.x & 7;          // own h-block id
    const int n0    = tile * NTILE;
    const int h0    = j_own * HTILE;
    const int hA    = h0 + 2 * lane;           // contiguous h pair
    const int hB    = hA + 1;

    const int  j_src   = w >> 1;               // producer this warp consumes
    const bool is_self = (j_src == j_own);

    // --- persistent weight registers: rows hA,hB, k in [32w, 32w+32) -------
    u64 wA[16], wB[16];
    {
        const u64* pa = (const u64*)&Whh_w[(size_t)hA * HID + w * 32];
        const u64* pb = (const u64*)&Whh_w[(size_t)hB * HID + w * 32];
#pragma unroll
        for (int i = 0; i < 16; i++) { wA[i] = pa[i]; wB[i] = pb[i]; }
    }

    unsigned int smem_w_base;
    {
        unsigned int a;
        asm("{ .reg .u64 t; cvta.to.shared.u64 t, %1; cvt.u32.u64 %0, t; }"
            : "=r"(a) : "l"(sm_h + w * 512));
        smem_w_base = a;
    }

    // epilogue ownership: thread (en, el) -> row n0+en, h-pair h0+2*el
    const int    en    = tid >> 5;
    const int    el    = tid & 31;
    const int    enab  = n0 + en;
    const float2 ebv   = *(const float2*)&Whh_b[h0 + 2 * el];
    // SMEM destination for own slice: warp 2*j_own + (el>=16), [n=en][kk=2el&31]
    float* sm_self = &sm_h[(2 * j_own + (el >> 4)) * 512 + en * 32 + ((2 * el) & 31)];

    unsigned* my_flag  = &g_flag[(tile * CL + j_own) * 64];
    unsigned* src_flag = &g_flag[(tile * CL + j_src) * 64];

    // preload step-0 gather
    float2 pv;
    {
        int xid = __ldg(&X[enab * LEN]);
        pv = __ldg((const float2*)&g_P[(size_t)xid * HID + h0 + 2 * el]);
    }

    for (int t = 0; t < LEN; t++) {
        float* dst = (t == LEN - 1) ? out : ((t & 1) ? g_h[1] : g_h[0]);
        const float* hin = (t & 1) ? g_h[0] : g_h[1];

        float sA = 0.f, sB = 0.f;

        if (t > 0) {
            if (!is_self) {
                // --- wait for our single producer, then pull its slice ------
                if (lane == 0) {
                    unsigned g;
                    do {
                        asm volatile("ld.acquire.gpu.u32 %0, [%1];"
                                     : "=r"(g) : "l"(src_flag) : "memory");
                    } while (g < (unsigned)t);
                }
                __syncwarp();
#pragma unroll
                for (int i = 0; i < 4; i++) {
                    int c  = i * 32 + lane;          // 16B chunk id (0..127)
                    int n  = c >> 3;
                    int kq = c & 7;
                    const float* src =
                        &hin[(size_t)(n0 + n) * HID + w * 32 + kq * 4];
                    asm volatile("cp.async.cg.shared.global [%0], [%1], 16;"
                                 :: "r"(smem_w_base + c * 16), "l"(src) : "memory");
                }
                asm volatile("cp.async.commit_group;" ::: "memory");
                asm volatile("cp.async.wait_group 0;" ::: "memory");
            }
            // (self warps: slice already in SMEM from last step's epilogue)

            // --- compute in two n-halves of 8 (register pressure) -----------
#pragma unroll
            for (int half = 0; half < 2; half++) {
                u64 aA[8], aB[8];
#pragma unroll
                for (int n = 0; n < 8; n++) { aA[n] = 0ULL; aB[n] = 0ULL; }
                const float* hp = sm_h + w * 512 + half * 8 * 32;
#pragma unroll
                for (int n = 0; n < 8; n++) {
                    const float4* row = (const float4*)(hp + n * 32);
                    u64 a0 = aA[n], a1 = aB[n];
#pragma unroll
                    for (int j = 0; j < 8; j++) {
                        float4 hv = row[j];
                        u64 lo = ((const u64*)&hv)[0];
                        u64 hi = ((const u64*)&hv)[1];
                        a0 = ffma2(lo, wA[2 * j],     a0);
                        a0 = ffma2(hi, wA[2 * j + 1], a0);
                        a1 = ffma2(lo, wB[2 * j],     a1);
                        a1 = ffma2(hi, wB[2 * j + 1], a1);
                    }
                    aA[n] = a0; aB[n] = a1;
                }
#pragma unroll
                for (int n = 0; n < 8; n++) {
                    float2 fa = *(float2*)&aA[n];
                    float2 fb = *(float2*)&aB[n];
                    sm_red[w * 512 + (half * 8 + n) * 32 + lane] =
                        make_float2(fa.x + fa.y, fb.x + fb.y);
                }
            }
            __syncthreads();

            // --- k-group reduction: one (n, h-pair) output per thread --------
            float xa = 0.f, xb = 0.f, ya = 0.f, yb = 0.f;
#pragma unroll
            for (int g = 0; g < 16; g += 2) {
                float2 v0 = sm_red[g * 512 + tid];
                float2 v1 = sm_red[(g + 1) * 512 + tid];
                xa += v0.x; xb += v0.y;
                ya += v1.x; yb += v1.y;
            }
            sA = xa + ya; sB = xb + yb;
        }

        // --- fused epilogue: bias + P + tanh; publish to GMEM + own SMEM -----
        float2 o;
        o.x = tanhf(sA + ebv.x + pv.x);
        o.y = tanhf(sB + ebv.y + pv.y);
        *(float2*)&dst[(size_t)enab * HID + h0 + 2 * el] = o;
        *(float2*)sm_self = o;                 // self-warps read this next step

        if (t < LEN - 1) {
            // prefetch next step's gather (g_P immutable; hides under publish)
            int xid2 = __ldg(&X[enab * LEN + t + 1]);
            pv = __ldg((const float2*)&g_P[(size_t)xid2 * HID + h0 + 2 * el]);

            __syncthreads();                   // epilogue stores + STS done
            if (tid == 0) {
                asm volatile("fence.acq_rel.gpu;" ::: "memory");
                asm volatile("st.relaxed.gpu.u32 [%0], %1;"
                             :: "l"(my_flag), "r"((unsigned)(t + 1)) : "memory");
            }
        }
    }

    // --- end-of-kernel cleanup: last CTA of the group resets flags/counter --
    __syncthreads();
    if (tid == 0) {
        unsigned old;
        asm volatile("atom.acq_rel.gpu.global.add.u32 %0, [%1], %2;"
                     : "=r"(old) : "l"(&g_cnt[tile * 64]), "r"(1u) : "memory");
        if (old == CL - 1) {
#pragma unroll
            for (int j = 0; j < CL; j++)
                asm volatile("st.relaxed.gpu.u32 [%0], %1;"
                             :: "l"(&g_flag[(tile * CL + j) * 64]), "r"(0u)
                             : "memory");
            asm volatile("st.relaxed.gpu.u32 [%0], %1;"
                         :: "l"(&g_cnt[tile * 64]), "r"(0u) : "memory");
        }
    }
}

// ---------------------------------------------------------------------------
extern "C" void kernel_launch(void* const* d_in, const int* in_sizes, int n_in,
                              void* d_out, int out_size) {
    const int*   X     = (const int*)d_in[0];
    const float* emb   = (const float*)d_in[1];
    const float* Whh_w = (const float*)d_in[2];
    const float* Whh_b = (const float*)d_in[3];
    const float* Wxh_w = (const float*)d_in[4];
    const float* Wxh_b = (const float*)d_in[5];
    float* out = (float*)d_out;

    const size_t sm_proj = (size_t)(64 * (EMB + 4) + 8 * 32 * 36) * sizeof(float); // ~101 KB
    const size_t sm_rnn  = (size_t)(16 * 512) * sizeof(float)                      // 32 KB h
                         + (size_t)(16 * 512) * sizeof(float2);                    // 64 KB red
    cudaFuncSetAttribute(proj_kernel, cudaFuncAttributeMaxDynamicSharedMemorySize, (int)sm_proj);
    cudaFuncSetAttribute(rnn_kernel,  cudaFuncAttributeMaxDynamicSharedMemorySize, (int)sm_rnn);

    // 1) P = emb @ Wxh^T + Wxh_b
    proj_kernel<<<dim3(VOCAB / 32, HID / 32), 256, sm_proj>>>(emb, Wxh_w, Wxh_b);

    // 2) all 512 timesteps in one persistent launch
    rnn_kernel<<<GRID, NTHR, sm_rnn>>>(X, Whh_w, Whh_b, out);
}